// round 16
// baseline (speedup 1.0000x reference)
#include <cuda_runtime.h>
#include <cuda_fp16.h>
#include <cstdint>
#include <math.h>

#define Bn   16
#define En   1024
#define Hn   16
#define Nn   2048
#define EHn  64
#define BHn  256
#define NM1n 2047

// ---------------- scratch ----------------
__device__ float g_qstep[BHn * EHn];
__device__ float g_kstep[BHn * EHn];
__device__ float g_vstep[BHn * EHn];
__device__ float g_abr [BHn];
__device__ float g_atbsum_part[BHn * 4];
__device__ float g_avbot_part[BHn * 8 * EHn];
__device__ __half g_attnh[(size_t)Nn * Bn * En];  // A for GEMM (fp16)
__device__ __half g_wh[(size_t)En * En];          // W_out (fp16)

// ---------------- kernel 0: convert W_out to fp16 ----------------
__global__ __launch_bounds__(256) void whalf_kernel(const float* __restrict__ W) {
    int i = (blockIdx.x * 256 + threadIdx.x) * 8;
    float4 v0 = *(const float4*)(W + i);
    float4 v1 = *(const float4*)(W + i + 4);
    __half2 h[4];
    h[0] = __floats2half2_rn(v0.x, v0.y);
    h[1] = __floats2half2_rn(v0.z, v0.w);
    h[2] = __floats2half2_rn(v1.x, v1.y);
    h[3] = __floats2half2_rn(v1.z, v1.w);
    *(float4*)(g_wh + i) = *(float4*)h;
}

// ---------------- kernel 1: qkv projections ----------------
__global__ __launch_bounds__(256) void proj_kernel(
    const float* __restrict__ query, const float* __restrict__ key,
    const float* __restrict__ value, const float* __restrict__ W,
    const float* __restrict__ bias)
{
    int w = blockIdx.x * 8 + (threadIdx.x >> 5);
    int lane = threadIdx.x & 31;
    int c = w & 1023;
    int r = (w >> 10) & 15;
    int p = w >> 14;
    const float* in = (p == 0) ? query : (p == 1) ? key : value;
    const float* wr = W + (size_t)(p * En + c) * En;
    const float* ir = in + r * En;
    float acc = 0.f;
    for (int k = lane; k < En; k += 32) acc += ir[k] * wr[k];
    #pragma unroll
    for (int o = 16; o; o >>= 1) acc += __shfl_down_sync(0xffffffffu, acc, o);
    if (lane == 0) {
        acc += bias[p * En + c];
        int h = c >> 6, e = c & 63;
        int bh = r * Hn + h;
        if (p == 0)      g_qstep[bh * EHn + e] = acc * 0.125f;
        else if (p == 1) g_kstep[bh * EHn + e] = acc;
        else             g_vstep[bh * EHn + e] = acc;
    }
}

// ---------------- kernel 2: fused streaming (atb+avbot | alr+ew), one launch -------
// role 0,1: k_t dots + kt shift-copy + v weighted pass + v shift-copy (1024-s chunk)
// role 2-5: alr dots + q shift-copy + FUSED ew row (av/a_sum/attn) (512-n chunk)
__global__ __launch_bounds__(256) void stream_kernel(
    const float* __restrict__ k_t_mem, const float* __restrict__ q_mem,
    const float* __restrict__ v_mem,
    const float* __restrict__ a_sum_mem, const float* __restrict__ av_mem,
    float* __restrict__ kt_out, float* __restrict__ q_out,
    float* __restrict__ v_out,
    float* __restrict__ a_sum_out, float* __restrict__ av_out)
{
    int bh = blockIdx.x;
    int role = blockIdx.y;
    int tid = threadIdx.x;

    if (role < 2) {
        __shared__ float qs[EHn], ks[EHn];
        __shared__ float red[256];
        __shared__ float satb[1024];
        __shared__ float part[16][EHn];
        int ck = role;
        int s0 = ck * 1024;
        if (tid < EHn) {
            qs[tid] = g_qstep[bh * EHn + tid];
            ks[tid] = g_kstep[bh * EHn + tid];
        }
        __syncthreads();
        // pass 1: k_t dots + fused kt shift-copy
        const float* base  = k_t_mem + (size_t)bh * EHn * Nn;
        float*       obase = kt_out  + (size_t)bh * EHn * Nn;
        int s4 = s0 + tid * 4;
        float4 acc = make_float4(0.f, 0.f, 0.f, 0.f);
        bool last = (s4 + 4 >= Nn);
        #pragma unroll 4
        for (int e = 0; e < EHn; e++) {
            const float* row = base + (size_t)e * Nn;
            float4 a4 = __ldcs((const float4*)(row + s4));
            float nxt = last ? ks[e] : __ldcs(row + s4 + 4);
            float4 o4 = make_float4(a4.y, a4.z, a4.w, nxt);
            __stcs((float4*)(obase + (size_t)e * Nn + s4), o4);
            float q = qs[e];
            acc.x += q * a4.x; acc.y += q * a4.y; acc.z += q * a4.z; acc.w += q * a4.w;
        }
        float vals[4] = {acc.x, acc.y, acc.z, acc.w};
        float local = 0.f;
        #pragma unroll
        for (int j = 0; j < 4; j++) {
            int s = s4 + j;
            float a = expf(vals[j]);
            satb[tid * 4 + j] = a;          // satb[i] = exp(dot at s0+i)
            if (s >= 1) local += a;
        }
        red[tid] = local;
        __syncthreads();
        for (int st = 128; st; st >>= 1) {
            if (tid < st) red[tid] += red[tid + st];
            __syncthreads();
        }
        if (tid == 0) g_atbsum_part[bh * 4 + ck] = red[0];
        if (ck == 0) {
            __syncthreads();
            red[tid] = (tid < EHn) ? qs[tid] * ks[tid] : 0.f;
            __syncthreads();
            for (int st = 128; st; st >>= 1) {
                if (tid < st) red[tid] += red[tid + st];
                __syncthreads();
            }
            if (tid == 0) g_abr[bh] = expf(red[0]);
        }
        __syncthreads();
        // pass 2: avbot partials with fused v shift-copy
        int ex = tid & 15, ch = tid >> 4;
        const float* vbase  = v_mem + (size_t)bh * Nn * EHn;
        float*       vobase = v_out + (size_t)bh * Nn * EHn;
        int ilo = (ck == 0) ? 1 : 0;
        float4 acc2 = make_float4(0.f, 0.f, 0.f, 0.f);
        for (int i = ilo + ch; i < 1024; i += 16) {
            float4 v = __ldcs((const float4*)(vbase + (size_t)(s0 + i) * EHn + ex * 4));
            __stcs((float4*)(vobase + (size_t)(s0 + i - 1) * EHn + ex * 4), v);
            float w = satb[i];
            acc2.x += w * v.x; acc2.y += w * v.y; acc2.z += w * v.z; acc2.w += w * v.w;
        }
        *(float4*)&part[ch][ex * 4] = acc2;
        __syncthreads();
        if (tid < 16) {
            float4 t = make_float4(0.f, 0.f, 0.f, 0.f);
            #pragma unroll
            for (int c = 0; c < 16; c++) {
                float4 p = *(float4*)&part[c][tid * 4];
                t.x += p.x; t.y += p.y; t.z += p.z; t.w += p.w;
            }
            *(float4*)(g_avbot_part + ((size_t)bh * 8 + ck) * EHn + tid * 4) = t;
            if (ck == 1) {
                float4 vs = *(float4*)(g_vstep + bh * EHn + tid * 4);
                *(float4*)(vobase + (size_t)(Nn - 1) * EHn + tid * 4) = vs;
            }
        }
    } else {
        __shared__ float kold[EHn], ks[EHn], v0s[EHn], vss[EHn];
        int ck = role - 2;
        int lane = tid & 31, warp = tid >> 5;
        if (tid < EHn) {
            kold[tid] = k_t_mem[(size_t)bh * EHn * Nn + (size_t)tid * Nn];
            ks[tid]   = g_kstep[bh * EHn + tid];
            v0s[tid]  = v_mem[(size_t)bh * Nn * EHn + tid];   // v_mem row 0
            vss[tid]  = g_vstep[bh * EHn + tid];
        }
        __syncthreads();
        int r = lane >> 3;
        int sub = lane & 7;
        float4 k0a = *(float4*)&kold[sub * 8];
        float4 k0b = *(float4*)&kold[sub * 8 + 4];
        float4 ksa = *(float4*)&ks[sub * 8];
        float4 ksb = *(float4*)&ks[sub * 8 + 4];
        float4 v0a = *(float4*)&v0s[sub * 8];
        float4 v0b = *(float4*)&v0s[sub * 8 + 4];
        float4 vsa = *(float4*)&vss[sub * 8];
        float4 vsb = *(float4*)&vss[sub * 8 + 4];
        const float* qbase  = q_mem + (size_t)bh * Nn * EHn;
        float*       qobase = q_out + (size_t)bh * Nn * EHn;
        int b = bh >> 4, h = bh & 15;
        #pragma unroll 4
        for (int it = 0; it < 16; it++) {
            int n = ck * 512 + it * 32 + warp * 4 + r;
            const float* row = qbase + (size_t)n * EHn + sub * 8;
            float4 a = __ldcs((const float4*)row);
            float4 bq = __ldcs((const float4*)(row + 4));
            bool valid = (n >= 1);
            if (valid) {
                float* orow = qobase + (size_t)(n - 1) * EHn + sub * 8;
                __stcs((float4*)orow, a);
                __stcs((float4*)(orow + 4), bq);
            }
            float d0 = a.x * k0a.x + a.y * k0a.y + a.z * k0a.z + a.w * k0a.w
                     + bq.x * k0b.x + bq.y * k0b.y + bq.z * k0b.z + bq.w * k0b.w;
            float d1 = a.x * ksa.x + a.y * ksa.y + a.z * ksa.z + a.w * ksa.w
                     + bq.x * ksb.x + bq.y * ksb.y + bq.z * ksb.z + bq.w * ksb.w;
            #pragma unroll
            for (int o = 4; o; o >>= 1) {
                d0 += __shfl_down_sync(0xffffffffu, d0, o, 8);
                d1 += __shfl_down_sync(0xffffffffu, d1, o, 8);
            }
            d0 = __shfl_sync(0xffffffffu, d0, 0, 8);   // broadcast group sum
            d1 = __shfl_sync(0xffffffffu, d1, 0, 8);
            if (valid) {
                // fused ew for row m = n-1 (main branch)
                int m = n - 1;
                float al0 = expf(d0), al1 = expf(d1);
                float asum = a_sum_mem[bh * NM1n + m] + al1 - al0;
                const float* avrow = av_mem + ((size_t)bh * NM1n + m) * EHn + sub * 8;
                float4 av0 = __ldcs((const float4*)avrow);
                float4 av1 = __ldcs((const float4*)(avrow + 4));
                av0.x = av0.x - al0 * v0a.x + al1 * vsa.x;
                av0.y = av0.y - al0 * v0a.y + al1 * vsa.y;
                av0.z = av0.z - al0 * v0a.z + al1 * vsa.z;
                av0.w = av0.w - al0 * v0a.w + al1 * vsa.w;
                av1.x = av1.x - al0 * v0b.x + al1 * vsb.x;
                av1.y = av1.y - al0 * v0b.y + al1 * vsb.y;
                av1.z = av1.z - al0 * v0b.z + al1 * vsb.z;
                av1.w = av1.w - al0 * v0b.w + al1 * vsb.w;
                float rs = 1.0f / asum;
                __half2 hh[4];
                hh[0] = __floats2half2_rn(av0.x * rs, av0.y * rs);
                hh[1] = __floats2half2_rn(av0.z * rs, av0.w * rs);
                hh[2] = __floats2half2_rn(av1.x * rs, av1.y * rs);
                hh[3] = __floats2half2_rn(av1.z * rs, av1.w * rs);
                __half* attn_row = g_attnh + ((size_t)(m * Bn + b) * En + h * EHn) + sub * 8;
                *(uint4*)attn_row = *(uint4*)hh;
                if (m >= 1) {
                    float* avo = av_out + ((size_t)bh * NM1n + (m - 1)) * EHn + sub * 8;
                    __stcs((float4*)avo, av0);
                    __stcs((float4*)(avo + 4), av1);
                    if (sub == 0) a_sum_out[bh * NM1n + m - 1] = asum;
                }
            }
        }
        if (ck == 3 && tid < EHn)
            qobase[(size_t)(Nn - 1) * EHn + tid] = g_qstep[bh * EHn + tid];
    }
}

// ---------------- kernel 3: ew tail (bottom row n = Nn-1) ----------------
__global__ __launch_bounds__(64) void ew_tail_kernel(
    float* __restrict__ a_sum_out, float* __restrict__ av_out)
{
    int bh = blockIdx.x;
    int e = threadIdx.x;
    int b = bh >> 4, h = bh & 15;
    float abr = g_abr[bh];
    float asum = g_atbsum_part[bh * 4] + g_atbsum_part[bh * 4 + 1] + abr;
    float av = abr * g_vstep[bh * EHn + e];
    av += g_avbot_part[((size_t)bh * 8 + 0) * EHn + e];
    av += g_avbot_part[((size_t)bh * 8 + 1) * EHn + e];
    g_attnh[((size_t)(NM1n * Bn + b) * En + h * EHn) + e] = __float2half_rn(av / asum);
    av_out[((size_t)bh * NM1n + NM1n - 1) * EHn + e] = av;
    if (e == 0) a_sum_out[bh * NM1n + NM1n - 1] = asum;
}

// ---------------- kernel 4: out = attn @ W^T + bias (fp16 mma.m16n8k16) ------
__device__ __forceinline__ void mma_f16(float c[4], const unsigned a[4], const unsigned b[2]) {
    asm volatile(
        "mma.sync.aligned.m16n8k16.row.col.f32.f16.f16.f32 "
        "{%0,%1,%2,%3},{%4,%5,%6,%7},{%8,%9},{%0,%1,%2,%3};\n"
        : "+f"(c[0]), "+f"(c[1]), "+f"(c[2]), "+f"(c[3])
        : "r"(a[0]), "r"(a[1]), "r"(a[2]), "r"(a[3]), "r"(b[0]), "r"(b[1]));
}
__device__ __forceinline__ void ldsm4(unsigned& r0, unsigned& r1, unsigned& r2, unsigned& r3,
                                      unsigned addr) {
    asm volatile("ldmatrix.sync.aligned.m8n8.x4.shared.b16 {%0,%1,%2,%3}, [%4];"
                 : "=r"(r0), "=r"(r1), "=r"(r2), "=r"(r3) : "r"(addr));
}
__device__ __forceinline__ void cpa16(unsigned dst, const void* src) {
    asm volatile("cp.async.cg.shared.global [%0], [%1], 16;" :: "r"(dst), "l"(src));
}

#define KB 32             // halves per K-tile
#define LDP 40            // padded row stride in halves (80B -> conflict-free ldmatrix)
#define ABYTES (128 * LDP * 2)     // 10240
#define STAGE_BYTES (2 * ABYTES)   // 20480
#define GEMM_SMEM (3 * STAGE_BYTES)

__global__ __launch_bounds__(256, 2) void gemm_kernel(
    const float* __restrict__ bias, float* __restrict__ out)
{
    extern __shared__ __half smh[];
    unsigned sbase;
    asm("{ .reg .u64 t; cvta.to.shared.u64 t, %1; cvt.u32.u64 %0, t; }"
        : "=r"(sbase) : "l"(smh));
    const int K = En;
    int tid = threadIdx.x;
    int warp = tid >> 5, lane = tid & 31;
    int warp_m = warp >> 2, warp_n = warp & 3;
    int m0 = blockIdx.y * 128;
    int n0 = blockIdx.x * 128;
    const __half* Ag = g_attnh + (size_t)m0 * K;
    const __half* Bg = g_wh + (size_t)n0 * K;

    int lrow = tid >> 2;
    int lcol = (tid & 3) << 3;

    float c[4][4][4];
    #pragma unroll
    for (int i = 0; i < 4; i++)
        #pragma unroll
        for (int j = 0; j < 4; j++)
            #pragma unroll
            for (int k = 0; k < 4; k++) c[i][j][k] = 0.f;

    #pragma unroll
    for (int t = 0; t < 2; t++) {
        int kb = t * KB;
        unsigned s = sbase + t * STAGE_BYTES;
        cpa16(s + (lrow * LDP + lcol) * 2,                 Ag + (size_t)lrow * K + kb + lcol);
        cpa16(s + ((lrow + 64) * LDP + lcol) * 2,          Ag + (size_t)(lrow + 64) * K + kb + lcol);
        cpa16(s + ABYTES + (lrow * LDP + lcol) * 2,        Bg + (size_t)lrow * K + kb + lcol);
        cpa16(s + ABYTES + ((lrow + 64) * LDP + lcol) * 2, Bg + (size_t)(lrow + 64) * K + kb + lcol);
        asm volatile("cp.async.commit_group;");
    }

    const int T = K / KB;   // 32
    unsigned stage_off[3] = {0u, (unsigned)STAGE_BYTES, (unsigned)(2 * STAGE_BYTES)};
    int a_row  = (lane & 7) + ((lane >> 3) & 1) * 8;
    int a_koff = (lane >> 4) * 8;
    int b_nrow = lane & 7;
    int b_noff = ((lane >> 4) & 1) * 8;
    int b_koff = ((lane >> 3) & 1) * 8;

    for (int t = 0; t < T; t++) {
        if (t < T - 1) { asm volatile("cp.async.wait_group 1;"); }
        else           { asm volatile("cp.async.wait_group 0;"); }
        __syncthreads();
        if (t + 2 < T) {
            int kb = (t + 2) * KB;
            unsigned s = sbase + stage_off[(t + 2) % 3];
            cpa16(s + (lrow * LDP + lcol) * 2,                 Ag + (size_t)lrow * K + kb + lcol);
            cpa16(s + ((lrow + 64) * LDP + lcol) * 2,          Ag + (size_t)(lrow + 64) * K + kb + lcol);
            cpa16(s + ABYTES + (lrow * LDP + lcol) * 2,        Bg + (size_t)lrow * K + kb + lcol);
            cpa16(s + ABYTES + ((lrow + 64) * LDP + lcol) * 2, Bg + (size_t)(lrow + 64) * K + kb + lcol);
            asm volatile("cp.async.commit_group;");
        }
        unsigned sA = sbase + stage_off[t % 3];
        unsigned sB = sA + ABYTES;
        #pragma unroll
        for (int kk = 0; kk < KB; kk += 16) {
            unsigned a[4][4], bf[4][2];
            #pragma unroll
            for (int mf = 0; mf < 4; mf++) {
                int r = warp_m * 64 + mf * 16 + a_row;
                ldsm4(a[mf][0], a[mf][1], a[mf][2], a[mf][3],
                      sA + (unsigned)(r * LDP + kk + a_koff) * 2);
            }
            #pragma unroll
            for (int pp = 0; pp < 2; pp++) {
                int bn = warp_n * 32 + pp * 16 + b_noff + b_nrow;
                ldsm4(bf[2 * pp][0], bf[2 * pp][1], bf[2 * pp + 1][0], bf[2 * pp + 1][1],
                      sB + (unsigned)(bn * LDP + kk + b_koff) * 2);
            }
            #pragma unroll
            for (int mf = 0; mf < 4; mf++)
                #pragma unroll
                for (int nf = 0; nf < 4; nf++)
                    mma_f16(c[mf][nf], a[mf], bf[nf]);
        }
    }

    #pragma unroll
    for (int mf = 0; mf < 4; mf++) {
        int r = m0 + warp_m * 64 + mf * 16 + (lane >> 2);
        #pragma unroll
        for (int nf = 0; nf < 4; nf++) {
            int cc = n0 + warp_n * 32 + nf * 8 + ((lane & 3) << 1);
            float b0 = bias[cc], b1 = bias[cc + 1];
            out[(size_t)r * En + cc]           = c[mf][nf][0] + b0;
            out[(size_t)r * En + cc + 1]       = c[mf][nf][1] + b1;
            out[(size_t)(r + 8) * En + cc]     = c[mf][nf][2] + b0;
            out[(size_t)(r + 8) * En + cc + 1] = c[mf][nf][3] + b1;
        }
    }
}

// ---------------- launch ----------------
extern "C" void kernel_launch(void* const* d_in, const int* in_sizes, int n_in,
                              void* d_out, int out_size)
{
    const float* query     = (const float*)d_in[0];
    const float* key       = (const float*)d_in[1];
    const float* value     = (const float*)d_in[2];
    const float* a_sum_mem = (const float*)d_in[3];
    const float* av_mem    = (const float*)d_in[4];
    const float* q_mem     = (const float*)d_in[5];
    const float* k_t_mem   = (const float*)d_in[6];
    const float* v_mem     = (const float*)d_in[7];
    const float* ipw       = (const float*)d_in[8];
    const float* ipb       = (const float*)d_in[9];
    const float* opw       = (const float*)d_in[10];
    const float* opb       = (const float*)d_in[11];

    float* out       = (float*)d_out;
    float* a_sum_out = out + (size_t)Nn * Bn * En;
    float* av_out    = a_sum_out + (size_t)BHn * NM1n;
    float* q_out     = av_out + (size_t)BHn * NM1n * EHn;
    float* kt_out    = q_out + (size_t)BHn * Nn * EHn;
    float* v_out     = kt_out + (size_t)BHn * Nn * EHn;

    cudaFuncSetAttribute(gemm_kernel, cudaFuncAttributeMaxDynamicSharedMemorySize, GEMM_SMEM);

    whalf_kernel<<<En * En / 2048, 256>>>(opw);
    proj_kernel<<<6144, 256>>>(query, key, value, ipw, ipb);
    stream_kernel<<<dim3(BHn, 6), 256>>>(k_t_mem, q_mem, v_mem, a_sum_mem, av_mem,
                                         kt_out, q_out, v_out, a_sum_out, av_out);
    ew_tail_kernel<<<BHn, 64>>>(a_sum_out, av_out);
    dim3 g(En / 128, (Nn * Bn) / 128);
    gemm_kernel<<<g, 256, GEMM_SMEM>>>(opb, out);
}

// round 17
// speedup vs baseline: 1.0473x; 1.0473x over previous
#include <cuda_runtime.h>
#include <cuda_fp16.h>
#include <cstdint>
#include <math.h>

#define Bn   16
#define En   1024
#define Hn   16
#define Nn   2048
#define EHn  64
#define BHn  256
#define NM1n 2047

// ---------------- scratch ----------------
__device__ float g_qstep[BHn * EHn];
__device__ float g_kstep[BHn * EHn];
__device__ float g_vstep[BHn * EHn];
__device__ float g_alr0[BHn * NM1n];
__device__ float g_alr1[BHn * NM1n];
__device__ float g_abr [BHn];
__device__ float g_atbsum_part[BHn * 4];
__device__ float g_avbot_part[BHn * 8 * EHn];
__device__ __half g_attnh[(size_t)Nn * Bn * En];  // A for GEMM (fp16)
__device__ __half g_wh[(size_t)En * En];          // W_out (fp16)

// ---------------- kernel 1: fused W-convert + qkv projections ----------------
// blocks [0,512): convert W_out to fp16; blocks [512, 6656): proj (warp/output)
__global__ __launch_bounds__(256) void proj_kernel(
    const float* __restrict__ query, const float* __restrict__ key,
    const float* __restrict__ value, const float* __restrict__ W,
    const float* __restrict__ bias, const float* __restrict__ Wout)
{
    int bx = blockIdx.x;
    if (bx < 512) {
        int i = (bx * 256 + threadIdx.x) * 8;
        float4 v0 = *(const float4*)(Wout + i);
        float4 v1 = *(const float4*)(Wout + i + 4);
        __half2 h[4];
        h[0] = __floats2half2_rn(v0.x, v0.y);
        h[1] = __floats2half2_rn(v0.z, v0.w);
        h[2] = __floats2half2_rn(v1.x, v1.y);
        h[3] = __floats2half2_rn(v1.z, v1.w);
        *(float4*)(g_wh + i) = *(float4*)h;
        return;
    }
    int w = (bx - 512) * 8 + (threadIdx.x >> 5);
    int lane = threadIdx.x & 31;
    int c = w & 1023;
    int r = (w >> 10) & 15;
    int p = w >> 14;
    const float* in = (p == 0) ? query : (p == 1) ? key : value;
    const float* wr = W + (size_t)(p * En + c) * En;
    const float* ir = in + r * En;
    float acc = 0.f;
    #pragma unroll
    for (int k = 0; k < 8; k++) {
        float4 wv = *(const float4*)(wr + lane * 4 + k * 128);
        float4 iv = *(const float4*)(ir + lane * 4 + k * 128);
        acc += wv.x * iv.x + wv.y * iv.y + wv.z * iv.z + wv.w * iv.w;
    }
    #pragma unroll
    for (int o = 16; o; o >>= 1) acc += __shfl_down_sync(0xffffffffu, acc, o);
    if (lane == 0) {
        acc += bias[p * En + c];
        int h = c >> 6, e = c & 63;
        int bh = r * Hn + h;
        if (p == 0)      g_qstep[bh * EHn + e] = acc * 0.125f;
        else if (p == 1) g_kstep[bh * EHn + e] = acc;
        else             g_vstep[bh * EHn + e] = acc;
    }
}

// ---------------- kernel 2: fused streaming (atb+avbot | alr), one launch ----------
// role 0,1: k_t dots + kt shift-copy + v weighted pass + v shift-copy (1024-s chunk)
// role 2-5: alr dots + q shift-copy (512-n chunk)
__global__ __launch_bounds__(256) void stream_kernel(
    const float* __restrict__ k_t_mem, const float* __restrict__ q_mem,
    const float* __restrict__ v_mem,
    float* __restrict__ kt_out, float* __restrict__ q_out,
    float* __restrict__ v_out)
{
    int bh = blockIdx.x;
    int role = blockIdx.y;
    int tid = threadIdx.x;

    if (role < 2) {
        __shared__ float qs[EHn], ks[EHn];
        __shared__ float red[256];
        __shared__ float satb[1024];
        __shared__ float part[16][EHn];
        int ck = role;
        int s0 = ck * 1024;
        if (tid < EHn) {
            qs[tid] = g_qstep[bh * EHn + tid];
            ks[tid] = g_kstep[bh * EHn + tid];
        }
        __syncthreads();
        // pass 1: k_t dots + fused kt shift-copy
        const float* base  = k_t_mem + (size_t)bh * EHn * Nn;
        float*       obase = kt_out  + (size_t)bh * EHn * Nn;
        int s4 = s0 + tid * 4;
        float4 acc = make_float4(0.f, 0.f, 0.f, 0.f);
        bool last = (s4 + 4 >= Nn);
        #pragma unroll 4
        for (int e = 0; e < EHn; e++) {
            const float* row = base + (size_t)e * Nn;
            float4 a4 = __ldcs((const float4*)(row + s4));
            float nxt = last ? ks[e] : __ldcs(row + s4 + 4);
            float4 o4 = make_float4(a4.y, a4.z, a4.w, nxt);
            __stcs((float4*)(obase + (size_t)e * Nn + s4), o4);
            float q = qs[e];
            acc.x += q * a4.x; acc.y += q * a4.y; acc.z += q * a4.z; acc.w += q * a4.w;
        }
        float vals[4] = {acc.x, acc.y, acc.z, acc.w};
        float local = 0.f;
        #pragma unroll
        for (int j = 0; j < 4; j++) {
            int s = s4 + j;
            float a = expf(vals[j]);
            satb[tid * 4 + j] = a;          // satb[i] = exp(dot at s0+i)
            if (s >= 1) local += a;
        }
        red[tid] = local;
        __syncthreads();
        for (int st = 128; st; st >>= 1) {
            if (tid < st) red[tid] += red[tid + st];
            __syncthreads();
        }
        if (tid == 0) g_atbsum_part[bh * 4 + ck] = red[0];
        if (ck == 0) {
            __syncthreads();
            red[tid] = (tid < EHn) ? qs[tid] * ks[tid] : 0.f;
            __syncthreads();
            for (int st = 128; st; st >>= 1) {
                if (tid < st) red[tid] += red[tid + st];
                __syncthreads();
            }
            if (tid == 0) g_abr[bh] = expf(red[0]);
        }
        __syncthreads();
        // pass 2: avbot partials with fused v shift-copy
        int ex = tid & 15, ch = tid >> 4;
        const float* vbase  = v_mem + (size_t)bh * Nn * EHn;
        float*       vobase = v_out + (size_t)bh * Nn * EHn;
        int ilo = (ck == 0) ? 1 : 0;
        float4 acc2 = make_float4(0.f, 0.f, 0.f, 0.f);
        for (int i = ilo + ch; i < 1024; i += 16) {
            float4 v = __ldcs((const float4*)(vbase + (size_t)(s0 + i) * EHn + ex * 4));
            __stcs((float4*)(vobase + (size_t)(s0 + i - 1) * EHn + ex * 4), v);
            float w = satb[i];
            acc2.x += w * v.x; acc2.y += w * v.y; acc2.z += w * v.z; acc2.w += w * v.w;
        }
        *(float4*)&part[ch][ex * 4] = acc2;
        __syncthreads();
        if (tid < 16) {
            float4 t = make_float4(0.f, 0.f, 0.f, 0.f);
            #pragma unroll
            for (int c = 0; c < 16; c++) {
                float4 p = *(float4*)&part[c][tid * 4];
                t.x += p.x; t.y += p.y; t.z += p.z; t.w += p.w;
            }
            *(float4*)(g_avbot_part + ((size_t)bh * 8 + ck) * EHn + tid * 4) = t;
            if (ck == 1) {
                float4 vs = *(float4*)(g_vstep + bh * EHn + tid * 4);
                *(float4*)(vobase + (size_t)(Nn - 1) * EHn + tid * 4) = vs;
            }
        }
    } else {
        __shared__ float kold[EHn], ks[EHn];
        int ck = role - 2;
        int lane = tid & 31, warp = tid >> 5;
        if (tid < EHn) {
            kold[tid] = k_t_mem[(size_t)bh * EHn * Nn + (size_t)tid * Nn];
            ks[tid]   = g_kstep[bh * EHn + tid];
        }
        __syncthreads();
        int r = lane >> 3;
        int sub = lane & 7;
        float4 k0a = *(float4*)&kold[sub * 8];
        float4 k0b = *(float4*)&kold[sub * 8 + 4];
        float4 ksa = *(float4*)&ks[sub * 8];
        float4 ksb = *(float4*)&ks[sub * 8 + 4];
        const float* qbase  = q_mem + (size_t)bh * Nn * EHn;
        float*       qobase = q_out + (size_t)bh * Nn * EHn;
        #pragma unroll 8
        for (int it = 0; it < 16; it++) {
            int n = ck * 512 + it * 32 + warp * 4 + r;
            const float* row = qbase + (size_t)n * EHn + sub * 8;
            float4 a = __ldcs((const float4*)row);
            float4 b = __ldcs((const float4*)(row + 4));
            bool valid = (n >= 1);
            if (valid) {
                float* orow = qobase + (size_t)(n - 1) * EHn + sub * 8;
                __stcs((float4*)orow, a);
                __stcs((float4*)(orow + 4), b);
            }
            float d0 = a.x * k0a.x + a.y * k0a.y + a.z * k0a.z + a.w * k0a.w
                     + b.x * k0b.x + b.y * k0b.y + b.z * k0b.z + b.w * k0b.w;
            float d1 = a.x * ksa.x + a.y * ksa.y + a.z * ksa.z + a.w * ksa.w
                     + b.x * ksb.x + b.y * ksb.y + b.z * ksb.z + b.w * ksb.w;
            #pragma unroll
            for (int o = 4; o; o >>= 1) {
                d0 += __shfl_down_sync(0xffffffffu, d0, o, 8);
                d1 += __shfl_down_sync(0xffffffffu, d1, o, 8);
            }
            if (sub == 0 && valid) {
                g_alr0[bh * NM1n + n - 1] = expf(d0);
                g_alr1[bh * NM1n + n - 1] = expf(d1);
            }
        }
        if (ck == 3 && tid < EHn)
            qobase[(size_t)(Nn - 1) * EHn + tid] = g_qstep[bh * EHn + tid];
    }
}

// ---------------- kernel 3: av_top / a_sum / attn (fp16, vectorized) ----------------
__global__ __launch_bounds__(256) void ew_kernel(
    const float* __restrict__ a_sum_mem, const float* __restrict__ av_mem,
    const float* __restrict__ v_mem,
    float* __restrict__ a_sum_out, float* __restrict__ av_out)
{
    int tid = threadIdx.x;
    int ex = tid & 15;
    int gid = tid >> 4;
    int rid = blockIdx.x * 16 + gid;
    int bh = rid >> 11, n = rid & (Nn - 1);
    int b = bh >> 4, h = bh & 15;
    int e4 = ex * 4;
    __half* attn_row = g_attnh + ((size_t)(n * Bn + b) * En + h * EHn) + e4;
    if (n < NM1n) {
        float al0 = 0.f, al1 = 0.f, asum = 0.f;
        if (ex == 0) {
            al0 = g_alr0[bh * NM1n + n];
            al1 = g_alr1[bh * NM1n + n];
            asum = a_sum_mem[bh * NM1n + n] + al1 - al0;
        }
        al0  = __shfl_sync(0xffffffffu, al0, 0, 16);
        al1  = __shfl_sync(0xffffffffu, al1, 0, 16);
        asum = __shfl_sync(0xffffffffu, asum, 0, 16);
        float4 v0 = *(const float4*)(v_mem + (size_t)bh * Nn * EHn + e4);
        float4 vs = *(const float4*)(g_vstep + bh * EHn + e4);
        float4 av = __ldcs((const float4*)(av_mem + ((size_t)bh * NM1n + n) * EHn + e4));
        av.x = av.x - al0 * v0.x + al1 * vs.x;
        av.y = av.y - al0 * v0.y + al1 * vs.y;
        av.z = av.z - al0 * v0.z + al1 * vs.z;
        av.w = av.w - al0 * v0.w + al1 * vs.w;
        float rs = 1.0f / asum;
        __half2 h01 = __floats2half2_rn(av.x * rs, av.y * rs);
        __half2 h23 = __floats2half2_rn(av.z * rs, av.w * rs);
        uint2 packed = make_uint2(*(unsigned*)&h01, *(unsigned*)&h23);
        *(uint2*)attn_row = packed;
        if (n >= 1) {
            __stcs((float4*)(av_out + ((size_t)bh * NM1n + (n - 1)) * EHn + e4), av);
            if (ex == 0) a_sum_out[bh * NM1n + n - 1] = asum;
        }
    } else {
        float abr = g_abr[bh];
        float asum = g_atbsum_part[bh * 4] + g_atbsum_part[bh * 4 + 1] + abr;
        float4 vs = *(const float4*)(g_vstep + bh * EHn + e4);
        float4 av = make_float4(abr * vs.x, abr * vs.y, abr * vs.z, abr * vs.w);
        #pragma unroll
        for (int c = 0; c < 2; c++) {
            float4 p = *(const float4*)(g_avbot_part + ((size_t)bh * 8 + c) * EHn + e4);
            av.x += p.x; av.y += p.y; av.z += p.z; av.w += p.w;
        }
        float rs = 1.0f / asum;
        __half2 h01 = __floats2half2_rn(av.x * rs, av.y * rs);
        __half2 h23 = __floats2half2_rn(av.z * rs, av.w * rs);
        uint2 packed = make_uint2(*(unsigned*)&h01, *(unsigned*)&h23);
        *(uint2*)attn_row = packed;
        *(float4*)(av_out + ((size_t)bh * NM1n + NM1n - 1) * EHn + e4) = av;
        if (ex == 0) a_sum_out[bh * NM1n + NM1n - 1] = asum;
    }
}

// ---------------- kernel 4: out = attn @ W^T + bias (fp16 mma.m16n8k16) ------
__device__ __forceinline__ void mma_f16(float c[4], const unsigned a[4], const unsigned b[2]) {
    asm volatile(
        "mma.sync.aligned.m16n8k16.row.col.f32.f16.f16.f32 "
        "{%0,%1,%2,%3},{%4,%5,%6,%7},{%8,%9},{%0,%1,%2,%3};\n"
        : "+f"(c[0]), "+f"(c[1]), "+f"(c[2]), "+f"(c[3])
        : "r"(a[0]), "r"(a[1]), "r"(a[2]), "r"(a[3]), "r"(b[0]), "r"(b[1]));
}
__device__ __forceinline__ void ldsm4(unsigned& r0, unsigned& r1, unsigned& r2, unsigned& r3,
                                      unsigned addr) {
    asm volatile("ldmatrix.sync.aligned.m8n8.x4.shared.b16 {%0,%1,%2,%3}, [%4];"
                 : "=r"(r0), "=r"(r1), "=r"(r2), "=r"(r3) : "r"(addr));
}
__device__ __forceinline__ void cpa16(unsigned dst, const void* src) {
    asm volatile("cp.async.cg.shared.global [%0], [%1], 16;" :: "r"(dst), "l"(src));
}

#define KB 32             // halves per K-tile
#define LDP 40            // padded row stride in halves (80B -> conflict-free ldmatrix)
#define ABYTES (128 * LDP * 2)     // 10240
#define STAGE_BYTES (2 * ABYTES)   // 20480
#define GEMM_SMEM (3 * STAGE_BYTES)

__global__ __launch_bounds__(256, 2) void gemm_kernel(
    const float* __restrict__ bias, float* __restrict__ out)
{
    extern __shared__ __half smh[];
    unsigned sbase;
    asm("{ .reg .u64 t; cvta.to.shared.u64 t, %1; cvt.u32.u64 %0, t; }"
        : "=r"(sbase) : "l"(smh));
    const int K = En;
    int tid = threadIdx.x;
    int warp = tid >> 5, lane = tid & 31;
    int warp_m = warp >> 2, warp_n = warp & 3;
    int m0 = blockIdx.y * 128;
    int n0 = blockIdx.x * 128;
    const __half* Ag = g_attnh + (size_t)m0 * K;
    const __half* Bg = g_wh + (size_t)n0 * K;

    int lrow = tid >> 2;
    int lcol = (tid & 3) << 3;

    float c[4][4][4];
    #pragma unroll
    for (int i = 0; i < 4; i++)
        #pragma unroll
        for (int j = 0; j < 4; j++)
            #pragma unroll
            for (int k = 0; k < 4; k++) c[i][j][k] = 0.f;

    #pragma unroll
    for (int t = 0; t < 2; t++) {
        int kb = t * KB;
        unsigned s = sbase + t * STAGE_BYTES;
        cpa16(s + (lrow * LDP + lcol) * 2,                 Ag + (size_t)lrow * K + kb + lcol);
        cpa16(s + ((lrow + 64) * LDP + lcol) * 2,          Ag + (size_t)(lrow + 64) * K + kb + lcol);
        cpa16(s + ABYTES + (lrow * LDP + lcol) * 2,        Bg + (size_t)lrow * K + kb + lcol);
        cpa16(s + ABYTES + ((lrow + 64) * LDP + lcol) * 2, Bg + (size_t)(lrow + 64) * K + kb + lcol);
        asm volatile("cp.async.commit_group;");
    }

    const int T = K / KB;   // 32
    unsigned stage_off[3] = {0u, (unsigned)STAGE_BYTES, (unsigned)(2 * STAGE_BYTES)};
    int a_row  = (lane & 7) + ((lane >> 3) & 1) * 8;
    int a_koff = (lane >> 4) * 8;
    int b_nrow = lane & 7;
    int b_noff = ((lane >> 4) & 1) * 8;
    int b_koff = ((lane >> 3) & 1) * 8;

    for (int t = 0; t < T; t++) {
        if (t < T - 1) { asm volatile("cp.async.wait_group 1;"); }
        else           { asm volatile("cp.async.wait_group 0;"); }
        __syncthreads();
        if (t + 2 < T) {
            int kb = (t + 2) * KB;
            unsigned s = sbase + stage_off[(t + 2) % 3];
            cpa16(s + (lrow * LDP + lcol) * 2,                 Ag + (size_t)lrow * K + kb + lcol);
            cpa16(s + ((lrow + 64) * LDP + lcol) * 2,          Ag + (size_t)(lrow + 64) * K + kb + lcol);
            cpa16(s + ABYTES + (lrow * LDP + lcol) * 2,        Bg + (size_t)lrow * K + kb + lcol);
            cpa16(s + ABYTES + ((lrow + 64) * LDP + lcol) * 2, Bg + (size_t)(lrow + 64) * K + kb + lcol);
            asm volatile("cp.async.commit_group;");
        }
        unsigned sA = sbase + stage_off[t % 3];
        unsigned sB = sA + ABYTES;
        #pragma unroll
        for (int kk = 0; kk < KB; kk += 16) {
            unsigned a[4][4], bf[4][2];
            #pragma unroll
            for (int mf = 0; mf < 4; mf++) {
                int r = warp_m * 64 + mf * 16 + a_row;
                ldsm4(a[mf][0], a[mf][1], a[mf][2], a[mf][3],
                      sA + (unsigned)(r * LDP + kk + a_koff) * 2);
            }
            #pragma unroll
            for (int pp = 0; pp < 2; pp++) {
                int bn = warp_n * 32 + pp * 16 + b_noff + b_nrow;
                ldsm4(bf[2 * pp][0], bf[2 * pp][1], bf[2 * pp + 1][0], bf[2 * pp + 1][1],
                      sB + (unsigned)(bn * LDP + kk + b_koff) * 2);
            }
            #pragma unroll
            for (int mf = 0; mf < 4; mf++)
                #pragma unroll
                for (int nf = 0; nf < 4; nf++)
                    mma_f16(c[mf][nf], a[mf], bf[nf]);
        }
    }

    #pragma unroll
    for (int mf = 0; mf < 4; mf++) {
        int r = m0 + warp_m * 64 + mf * 16 + (lane >> 2);
        #pragma unroll
        for (int nf = 0; nf < 4; nf++) {
            int cc = n0 + warp_n * 32 + nf * 8 + ((lane & 3) << 1);
            float b0 = bias[cc], b1 = bias[cc + 1];
            out[(size_t)r * En + cc]           = c[mf][nf][0] + b0;
            out[(size_t)r * En + cc + 1]       = c[mf][nf][1] + b1;
            out[(size_t)(r + 8) * En + cc]     = c[mf][nf][2] + b0;
            out[(size_t)(r + 8) * En + cc + 1] = c[mf][nf][3] + b1;
        }
    }
}

// ---------------- launch ----------------
extern "C" void kernel_launch(void* const* d_in, const int* in_sizes, int n_in,
                              void* d_out, int out_size)
{
    const float* query     = (const float*)d_in[0];
    const float* key       = (const float*)d_in[1];
    const float* value     = (const float*)d_in[2];
    const float* a_sum_mem = (const float*)d_in[3];
    const float* av_mem    = (const float*)d_in[4];
    const float* q_mem     = (const float*)d_in[5];
    const float* k_t_mem   = (const float*)d_in[6];
    const float* v_mem     = (const float*)d_in[7];
    const float* ipw       = (const float*)d_in[8];
    const float* ipb       = (const float*)d_in[9];
    const float* opw       = (const float*)d_in[10];
    const float* opb       = (const float*)d_in[11];

    float* out       = (float*)d_out;
    float* a_sum_out = out + (size_t)Nn * Bn * En;
    float* av_out    = a_sum_out + (size_t)BHn * NM1n;
    float* q_out     = av_out + (size_t)BHn * NM1n * EHn;
    float* kt_out    = q_out + (size_t)BHn * Nn * EHn;
    float* v_out     = kt_out + (size_t)BHn * Nn * EHn;

    cudaFuncSetAttribute(gemm_kernel, cudaFuncAttributeMaxDynamicSharedMemorySize, GEMM_SMEM);

    proj_kernel<<<6656, 256>>>(query, key, value, ipw, ipb, opw);
    stream_kernel<<<dim3(BHn, 6), 256>>>(k_t_mem, q_mem, v_mem, kt_out, q_out, v_out);
    ew_kernel<<<BHn * Nn / 16, 256>>>(a_sum_mem, av_mem, v_mem, a_sum_out, av_out);
    dim3 g(En / 128, (Nn * Bn) / 128);
    gemm_kernel<<<g, 256, GEMM_SMEM>>>(opb, out);
}